// round 1
// baseline (speedup 1.0000x reference)
#include <cuda_runtime.h>
#include <math.h>

// Problem constants
#define NN   4096   // nodes
#define KK   32     // neighbors
#define CC   128    // channels
#define VV   21     // vocab

// ---------------- precomputed small tensors (device globals) ----------------
__device__ float g_base[CC];        // bl2 + r0 + be2   (r0 = c0@Wr2[:C] + br2)
__device__ float g_u0[CC];          // c0 @ Wl2[:C]
__device__ float g_T[VV][CC];       // W_s[v] @ Wl2[C:,:]
__device__ float g_TW[VV][VV];      // T[v] @ W_out
__device__ float g_g0[VV];          // (bl2+bo2)@W_out + b_out
__device__ float g_g1[VV];          // u0@W_out
__device__ float g_key[NN];         // (chain_M*mask + 1e-4)*|z|

// ---------------- precompute kernel (1 CTA) ----------------
__global__ void precompute_kernel(
    const float* __restrict__ bl1, const float* __restrict__ bo1,
    const float* __restrict__ Wl2, const float* __restrict__ bl2,
    const float* __restrict__ Wr2, const float* __restrict__ br2,
    const float* __restrict__ be2, const float* __restrict__ bo2,
    const float* __restrict__ W_s, const float* __restrict__ W_out,
    const float* __restrict__ b_out,
    const float* __restrict__ mask, const float* __restrict__ chain_M,
    const float* __restrict__ z)
{
    __shared__ float s_c0[CC];
    __shared__ float s_u0[CC];
    __shared__ float s_bb[CC];       // bl2 + bo2
    __shared__ float s_T[VV][CC];

    int t = threadIdx.x;

    if (t < CC) s_c0[t] = bl1[t] + bo1[t];
    __syncthreads();

    if (t < CC) {
        float u = 0.f, r = 0.f;
        for (int d = 0; d < CC; d++) {
            float c0 = s_c0[d];
            u += c0 * Wl2[d * CC + t];
            r += c0 * Wr2[d * CC + t];
        }
        s_u0[t]  = u;
        g_u0[t]  = u;
        g_base[t] = bl2[t] + r + br2[t] + be2[t];
        s_bb[t]  = bl2[t] + bo2[t];
    }

    // T[v][c] = sum_h W_s[v][h] * Wl2[(C+h)][c]
    for (int i = t; i < VV * CC; i += blockDim.x) {
        int v = i / CC, c = i % CC;
        float acc = 0.f;
        for (int hh = 0; hh < CC; hh++)
            acc += W_s[v * CC + hh] * Wl2[(CC + hh) * CC + c];
        s_T[v][c] = acc;
        g_T[v][c] = acc;
    }
    __syncthreads();

    // TW[v][w] = sum_c T[v][c] * W_out[c][w]
    for (int i = t; i < VV * VV; i += blockDim.x) {
        int v = i / VV, w = i % VV;
        float acc = 0.f;
        for (int c = 0; c < CC; c++)
            acc += s_T[v][c] * W_out[c * VV + w];
        g_TW[v][w] = acc;
    }

    if (t < VV) {
        float a0 = b_out[t], a1 = 0.f;
        for (int c = 0; c < CC; c++) {
            float wo = W_out[c * VV + t];
            a0 += s_bb[c] * wo;
            a1 += s_u0[c] * wo;
        }
        g_g0[t] = a0;
        g_g1[t] = a1;
    }

    // sorting keys: (chain_M*mask + 1e-4) * |z|  — keep mul/add unfused to
    // match the reference's rounding at potential ties
    for (int i = t; i < NN; i += blockDim.x) {
        float cm = __fadd_rn(__fmul_rn(chain_M[i], mask[i]), 1e-4f);
        g_key[i] = __fmul_rn(cm, fabsf(z[i]));
    }
}

// ---------------- main fused kernel ----------------
// One CTA = 256 threads = 2 nodes. Half h (128 threads) owns node n.
// Thread c owns channel c: computes ee[k][c] for all k (32 accumulators),
// then score epilogue with cross-thread reductions.
__global__ __launch_bounds__(256) void gat_main_kernel(
    const float* __restrict__ E,
    const int*   __restrict__ E_idx,
    const int*   __restrict__ S,
    const float* __restrict__ mask,
    const float* __restrict__ We2,
    const float* __restrict__ a2,
    float*       __restrict__ out)
{
    // E tile, transposed: sEt[h][d][k], padded to 36 floats for 16B-aligned rows
    __shared__ float sEt[2][CC][36];
    __shared__ float sPart[2][4][KK];
    __shared__ float sA[2][KK];     // mask_n * attend
    __shared__ int   sS[2][KK];     // S[E_idx[n,k]]
    __shared__ float sW[2][VV];     // vocab-binned alpha weights

    const int t    = threadIdx.x;
    const int h    = t >> 7;        // 0/1: which node of this CTA
    const int c    = t & 127;       // channel
    const int lane = t & 31;
    const int warp = (t >> 5) & 3;  // warp within half
    const int n    = blockIdx.x * 2 + h;

    // ---- load E[n] transposed into smem (coalesced gmem, conflict-lite smem) ----
    const float* En = E + (size_t)n * (KK * CC);
    #pragma unroll
    for (int k = 0; k < KK; k++)
        sEt[h][c][k] = En[k * CC + c];

    // ---- per-neighbor metadata ----
    if (c < KK) {
        int j = E_idx[n * KK + c];
        sS[h][c] = S[j];
        float kn = g_key[n], kj = g_key[j];
        float att = (kn > kj || (kn == kj && n > j)) ? 1.f : 0.f;
        sA[h][c] = mask[n] * att;
    }
    if (c < VV) sW[h][c] = 0.f;
    __syncthreads();

    // ---- GEMM: acc[k] = sum_d E[n][k][d] * We2[d][c] ----
    float acc[KK];
    #pragma unroll
    for (int k = 0; k < KK; k++) acc[k] = 0.f;

    #pragma unroll 4
    for (int d = 0; d < CC; d++) {
        float w = __ldg(&We2[d * CC + c]);            // coalesced, L1-hot
        const float4* row = (const float4*)sEt[h][d]; // broadcast reads
        #pragma unroll
        for (int kg = 0; kg < 8; kg++) {
            float4 e = row[kg];
            acc[kg * 4 + 0] += e.x * w;
            acc[kg * 4 + 1] += e.y * w;
            acc[kg * 4 + 2] += e.z * w;
            acc[kg * 4 + 3] += e.w * w;
        }
    }

    // ---- score epilogue: pre = ee + base + mask*u0 + a_nk*T[S_j]; leaky; dot a2 ----
    const float mask_n = mask[n];
    const float bpc = g_base[c] + mask_n * g_u0[c];
    const float a2c = a2[c];

    #pragma unroll
    for (int k = 0; k < KK; k++) {
        float pre = acc[k] + bpc + sA[h][k] * g_T[sS[h][k]][c];
        float m   = (pre >= 0.f) ? pre : 0.2f * pre;   // leaky_relu(0.2)
        float val = m * a2c;
        val += __shfl_xor_sync(0xffffffffu, val, 16);
        val += __shfl_xor_sync(0xffffffffu, val, 8);
        val += __shfl_xor_sync(0xffffffffu, val, 4);
        val += __shfl_xor_sync(0xffffffffu, val, 2);
        val += __shfl_xor_sync(0xffffffffu, val, 1);
        if (lane == 0) sPart[h][warp][k] = val;
    }
    __syncthreads();

    // ---- softmax over k (warps 0 and 4: c<32 is one full warp) ----
    if (c < KK) {
        int k = c;
        float sc = sPart[h][0][k] + sPart[h][1][k] + sPart[h][2][k] + sPart[h][3][k];
        float mx = sc;
        #pragma unroll
        for (int o = 16; o > 0; o >>= 1)
            mx = fmaxf(mx, __shfl_xor_sync(0xffffffffu, mx, o));
        float e = expf(sc - mx);
        float s = e;
        #pragma unroll
        for (int o = 16; o > 0; o >>= 1)
            s += __shfl_xor_sync(0xffffffffu, s, o);
        float alpha = e / s;
        atomicAdd(&sW[h][sS[h][k]], alpha * sA[h][k]);
    }
    __syncthreads();

    // ---- logits via 21x21 + log_softmax (one full warp per node) ----
    if (c < 32) {
        int v = c;
        float lg = -INFINITY;
        if (v < VV) {
            lg = g_g0[v] + mask_n * g_g1[v];
            #pragma unroll
            for (int u = 0; u < VV; u++)
                lg += sW[h][u] * g_TW[u][v];
        }
        float mx = lg;
        #pragma unroll
        for (int o = 16; o > 0; o >>= 1)
            mx = fmaxf(mx, __shfl_xor_sync(0xffffffffu, mx, o));
        float e = (v < VV) ? expf(lg - mx) : 0.f;
        float s = e;
        #pragma unroll
        for (int o = 16; o > 0; o >>= 1)
            s += __shfl_xor_sync(0xffffffffu, s, o);
        if (v < VV)
            out[n * VV + v] = lg - mx - logf(s);
    }
}

// ---------------- launch ----------------
extern "C" void kernel_launch(void* const* d_in, const int* in_sizes, int n_in,
                              void* d_out, int out_size)
{
    const float* E       = (const float*)d_in[0];
    const int*   E_idx   = (const int*)  d_in[1];
    const int*   S       = (const int*)  d_in[2];
    const float* mask    = (const float*)d_in[3];
    const float* chain_M = (const float*)d_in[4];
    const float* z       = (const float*)d_in[5];
    // layer-1 params: only bl1 (7) and bo1 (13) matter (x0 == 0)
    const float* bl1     = (const float*)d_in[7];
    const float* bo1     = (const float*)d_in[13];
    const float* Wl2     = (const float*)d_in[14];
    const float* bl2     = (const float*)d_in[15];
    const float* Wr2     = (const float*)d_in[16];
    const float* br2     = (const float*)d_in[17];
    const float* We2     = (const float*)d_in[18];
    const float* be2     = (const float*)d_in[19];
    const float* a2      = (const float*)d_in[20];
    const float* bo2     = (const float*)d_in[21];
    const float* W_s     = (const float*)d_in[22];
    const float* W_out   = (const float*)d_in[23];
    const float* b_out   = (const float*)d_in[24];

    float* out = (float*)d_out;

    precompute_kernel<<<1, 256>>>(bl1, bo1, Wl2, bl2, Wr2, br2, be2, bo2,
                                  W_s, W_out, b_out, mask, chain_M, z);
    gat_main_kernel<<<NN / 2, 256>>>(E, E_idx, S, mask, We2, a2, out);
}

// round 4
// speedup vs baseline: 3.7874x; 3.7874x over previous
#include <cuda_runtime.h>
#include <cuda_bf16.h>
#include <math.h>
#include <stdint.h>

#define NN 4096
#define KK 32
#define CC 128
#define VV 21

// ---------------- precomputed tensors (device globals) ----------------
__device__ float g_base[CC];                       // bl2 + (c0@Wr2 + br2) + be2
__device__ float g_u0[CC];                         // c0 @ Wl2[:C]
__device__ float g_T[VV][CC];                      // W_s[v] @ Wl2[C:]
__device__ float g_TW[VV][VV];                     // T @ W_out
__device__ float g_g0[VV];                         // (bl2+bo2)@W_out + b_out
__device__ float g_g1[VV];                         // u0@W_out
__device__ float g_key[NN];                        // (chain_M*mask+1e-4)*|z|
__device__ __align__(16) __nv_bfloat16 g_Bb[CC * CC]; // bf16(We2), [k][n] row-major

// ---------------- PTX helpers (plain sm_103-legal only) ----------------
__device__ __forceinline__ uint32_t smem_u32(const void* p) {
    uint32_t a;
    asm("{ .reg .u64 t; cvta.to.shared.u64 t, %1; cvt.u32.u64 %0, t; }" : "=r"(a) : "l"(p));
    return a;
}

__device__ __forceinline__ void ldmx4(uint32_t* r, uint32_t p) {
    asm volatile("ldmatrix.sync.aligned.m8n8.x4.shared.b16 {%0,%1,%2,%3}, [%4];"
                 : "=r"(r[0]), "=r"(r[1]), "=r"(r[2]), "=r"(r[3]) : "r"(p));
}
__device__ __forceinline__ void ldmx4t(uint32_t* r, uint32_t p) {
    asm volatile("ldmatrix.sync.aligned.m8n8.x4.trans.shared.b16 {%0,%1,%2,%3}, [%4];"
                 : "=r"(r[0]), "=r"(r[1]), "=r"(r[2]), "=r"(r[3]) : "r"(p));
}
__device__ __forceinline__ void mma16816(float* d, const uint32_t* a, uint32_t b0, uint32_t b1) {
    asm volatile(
        "mma.sync.aligned.m16n8k16.row.col.f32.bf16.bf16.f32 "
        "{%0,%1,%2,%3}, {%4,%5,%6,%7}, {%8,%9}, {%0,%1,%2,%3};"
        : "+f"(d[0]), "+f"(d[1]), "+f"(d[2]), "+f"(d[3])
        : "r"(a[0]), "r"(a[1]), "r"(a[2]), "r"(a[3]), "r"(b0), "r"(b1));
}

// ---------------- precompute kernel (grid=32, block=256) ----------------
__global__ void precompute_kernel(
    const float* __restrict__ bl1, const float* __restrict__ bo1,
    const float* __restrict__ Wl2, const float* __restrict__ bl2,
    const float* __restrict__ Wr2, const float* __restrict__ br2,
    const float* __restrict__ be2, const float* __restrict__ bo2,
    const float* __restrict__ We2,
    const float* __restrict__ W_s, const float* __restrict__ W_out,
    const float* __restrict__ b_out,
    const float* __restrict__ mask, const float* __restrict__ chain_M,
    const float* __restrict__ z)
{
    __shared__ float sh0[CC];
    __shared__ float sh1[CC];
    __shared__ float sh2[CC];
    const int b = blockIdx.x;
    const int t = threadIdx.x;

    // keys
    {
        int i = b * 256 + t;
        if (i < NN) {
            float cm = __fadd_rn(__fmul_rn(chain_M[i], mask[i]), 1e-4f);
            g_key[i] = __fmul_rn(cm, fabsf(z[i]));
        }
    }
    // We2 -> bf16 (row-major, no transpose: We2 is already [k][n])
    for (int i = b * 256 + t; i < CC * CC; i += 32 * 256)
        g_Bb[i] = __float2bfloat16(We2[i]);

    if (b < VV) {
        if (t < CC) {
            float acc = 0.f;
            for (int hh = 0; hh < CC; hh++)
                acc += W_s[b * CC + hh] * Wl2[(CC + hh) * CC + t];
            g_T[b][t] = acc;
            sh0[t] = acc;
        }
        __syncthreads();
        if (t < VV) {
            float acc = 0.f;
            for (int c = 0; c < CC; c++)
                acc += sh0[c] * W_out[c * VV + t];
            g_TW[b][t] = acc;
        }
    } else if (b == VV) {
        if (t < CC) sh0[t] = bl1[t] + bo1[t];         // c0
        __syncthreads();
        if (t < CC) {
            float u = 0.f, r = 0.f;
            for (int d = 0; d < CC; d++) {
                float c0 = sh0[d];
                u += c0 * Wl2[d * CC + t];
                r += c0 * Wr2[d * CC + t];
            }
            sh1[t] = u;  g_u0[t] = u;
            g_base[t] = bl2[t] + r + br2[t] + be2[t];
            sh2[t] = bl2[t] + bo2[t];
        }
        __syncthreads();
        if (t < VV) {
            float a0 = b_out[t], a1 = 0.f;
            for (int c = 0; c < CC; c++) {
                float wo = W_out[c * VV + t];
                a0 += sh2[c] * wo;
                a1 += sh1[c] * wo;
            }
            g_g0[t] = a0;
            g_g1[t] = a1;
        }
    }
}

// ---------------- main kernel smem ----------------
#define PAD 136   // bf16 row stride: 272 bytes -> ldmatrix conflict-free
struct SmemLayout {
    __nv_bfloat16 A[CC][PAD];   // E tile bf16
    __nv_bfloat16 B[CC][PAD];   // We2 bf16 [k][n]
    float T[VV][132];
    float BB[4][CC];            // g_base + mask_n*u0 per node
    float A2[CC];
    float G0[24], G1[24];
    float TW[VV][VV];
    float Am[4][KK];            // mask_n * attend
    int   Sv[4][KK];            // S[E_idx]
    float Wv[4][VV];            // vocab-binned alpha weights
    float Sc[4][KK];            // per-neighbor scores
    float Mk[4];
};

// ---------------- main fused MMA kernel ----------------
// CTA = 256 threads / 8 warps, 4 nodes. Warp w computes GEMM rows
// 16w..16w+15 (node w>>1, k = (w&1)*16 + 0..15) over ALL 128 channels.
__global__ __launch_bounds__(256) void gat_mma_kernel(
    const float* __restrict__ E,
    const int*   __restrict__ E_idx,
    const int*   __restrict__ S,
    const float* __restrict__ mask,
    const float* __restrict__ a2,
    float*       __restrict__ out)
{
    extern __shared__ char raw[];
    SmemLayout* sm = (SmemLayout*)raw;

    const int t    = threadIdx.x;
    const int lane = t & 31;
    const int wid  = t >> 5;
    const int b    = blockIdx.x;

    // ---- A: load E tile (128 x 128 fp32), cvt bf16, padded store ----
    {
        const float4* Eg = (const float4*)(E + (size_t)b * (CC * CC));
        #pragma unroll 4
        for (int i = t; i < 4096; i += 256) {
            int r = i >> 5, q = i & 31;            // row, float4-chunk
            float4 v = Eg[i];
            __nv_bfloat162 lo = __float22bfloat162_rn(make_float2(v.x, v.y));
            __nv_bfloat162 hi = __float22bfloat162_rn(make_float2(v.z, v.w));
            uint2 pk;
            pk.x = *(const uint32_t*)&lo;
            pk.y = *(const uint32_t*)&hi;
            *(uint2*)&sm->A[r][q * 4] = pk;
        }
    }
    // ---- B: copy We2 bf16 ----
    {
        const uint4* Bg = (const uint4*)g_Bb;
        #pragma unroll 2
        for (int i = t; i < 2048; i += 256) {
            int r = i >> 4, u = i & 15;            // row, uint4-chunk (8 vals)
            *(uint4*)&sm->B[r][u * 8] = Bg[i];
        }
    }
    // ---- small tables ----
    for (int i = t; i < VV * CC; i += 256) sm->T[i / CC][i % CC] = g_T[i / CC][i % CC];
    for (int i = t; i < 4 * CC; i += 256) {
        int h = i >> 7, c = i & 127;
        sm->BB[h][c] = g_base[c] + mask[b * 4 + h] * g_u0[c];
    }
    if (t < CC) sm->A2[t] = a2[t];
    if (t < VV) { sm->G0[t] = g_g0[t]; sm->G1[t] = g_g1[t]; }
    for (int i = t; i < VV * VV; i += 256) sm->TW[i / VV][i % VV] = g_TW[i / VV][i % VV];
    if (t < 128) {
        int h = t >> 5, k = t & 31;
        int n = b * 4 + h;
        int j = E_idx[n * KK + k];
        sm->Sv[h][k] = S[j];
        float kn = g_key[n], kj = g_key[j];
        float att = (kn > kj || (kn == kj && n > j)) ? 1.f : 0.f;
        sm->Am[h][k] = mask[n] * att;
    }
    if (t < 4) sm->Mk[t] = mask[b * 4 + t];
    for (int i = t; i < 4 * VV; i += 256) sm->Wv[i / VV][i % VV] = 0.f;
    __syncthreads();

    // ---- GEMM: warp tile 16x128, K=128 in 8 steps of 16 ----
    float acc[64];
    #pragma unroll
    for (int i = 0; i < 64; i++) acc[i] = 0.f;

    const int m0 = wid * 16;
    // ldmatrix A pointer: lane i -> row m0 + (i&15), col ks*16 + (i>>4)*8
    const uint32_t a_base = smem_u32(&sm->A[m0 + (lane & 15)][(lane >> 4) * 8]);
    // ldmatrix B pointer (trans): sub = lane>>3:
    //   row = ks*16 + (sub&1)*8 + (lane&7), col = n0 + (sub>>1)*8
    const int bsub = lane >> 3;
    const uint32_t b_base = smem_u32(
        &sm->B[(bsub & 1) * 8 + (lane & 7)][(bsub >> 1) * 8]);

    #pragma unroll
    for (int ks = 0; ks < 8; ks++) {
        uint32_t af[4];
        ldmx4(af, a_base + (uint32_t)(ks * 16) * 2);
        #pragma unroll
        for (int p = 0; p < 8; p++) {             // n-tile pairs: n0 = p*16
            uint32_t bf[4];
            ldmx4t(bf, b_base + (uint32_t)(ks * 16) * (PAD * 2) + (uint32_t)(p * 16) * 2);
            mma16816(&acc[(2 * p) * 4],     af, bf[0], bf[1]);
            mma16816(&acc[(2 * p + 1) * 4], af, bf[2], bf[3]);
        }
    }

    // ---- per-row score: leaky + dot(a2) ----
    {
        const int g   = lane >> 2;
        const int h   = wid >> 1;
        const int klo = (wid & 1) * 16 + g;
        const int khi = klo + 8;
        const float aA_lo = sm->Am[h][klo];
        const float aA_hi = sm->Am[h][khi];
        const float* Tlo = sm->T[sm->Sv[h][klo]];
        const float* Thi = sm->T[sm->Sv[h][khi]];

        float s_lo = 0.f, s_hi = 0.f;
        #pragma unroll
        for (int nt = 0; nt < 16; nt++) {
            const int c0 = nt * 8 + (lane & 3) * 2;
            const float bb0 = sm->BB[h][c0],     bb1 = sm->BB[h][c0 + 1];
            const float a20 = sm->A2[c0],        a21 = sm->A2[c0 + 1];
            const float tl0 = Tlo[c0], tl1 = Tlo[c0 + 1];
            const float th0 = Thi[c0], th1 = Thi[c0 + 1];

            float p0 = acc[nt * 4 + 0] + bb0 + aA_lo * tl0;
            float p1 = acc[nt * 4 + 1] + bb1 + aA_lo * tl1;
            float p2 = acc[nt * 4 + 2] + bb0 + aA_hi * th0;
            float p3 = acc[nt * 4 + 3] + bb1 + aA_hi * th1;
            p0 = fmaxf(p0, 0.2f * p0);
            p1 = fmaxf(p1, 0.2f * p1);
            p2 = fmaxf(p2, 0.2f * p2);
            p3 = fmaxf(p3, 0.2f * p3);
            s_lo = fmaf(p0, a20, s_lo);
            s_lo = fmaf(p1, a21, s_lo);
            s_hi = fmaf(p2, a20, s_hi);
            s_hi = fmaf(p3, a21, s_hi);
        }
        // reduce over the quad (lanes sharing groupID)
        s_lo += __shfl_xor_sync(0xffffffffu, s_lo, 1);
        s_lo += __shfl_xor_sync(0xffffffffu, s_lo, 2);
        s_hi += __shfl_xor_sync(0xffffffffu, s_hi, 1);
        s_hi += __shfl_xor_sync(0xffffffffu, s_hi, 2);
        if ((lane & 3) == 0) {
            sm->Sc[h][klo] = s_lo;
            sm->Sc[h][khi] = s_hi;
        }
    }
    __syncthreads();

    // ---- softmax over k + 21-bin logits + log_softmax (warp = node) ----
    if (t < 128) {
        const int h = wid;
        const int n = b * 4 + h;
        const float aA = sm->Am[h][lane];
        const int   sk = sm->Sv[h][lane];

        float score = sm->Sc[h][lane];
        float mx = score;
        #pragma unroll
        for (int o = 16; o > 0; o >>= 1)
            mx = fmaxf(mx, __shfl_xor_sync(0xffffffffu, mx, o));
        float e = expf(score - mx);
        float ssum = e;
        #pragma unroll
        for (int o = 16; o > 0; o >>= 1)
            ssum += __shfl_xor_sync(0xffffffffu, ssum, o);
        float wgt = (e / ssum) * aA;
        atomicAdd(&sm->Wv[h][sk], wgt);
        __syncwarp();

        float lg = -1e30f;
        if (lane < VV) {
            lg = sm->G0[lane] + sm->Mk[h] * sm->G1[lane];
            #pragma unroll
            for (int u = 0; u < VV; u++)
                lg = fmaf(sm->Wv[h][u], sm->TW[u][lane], lg);
        }
        float mx2 = lg;
        #pragma unroll
        for (int o = 16; o > 0; o >>= 1)
            mx2 = fmaxf(mx2, __shfl_xor_sync(0xffffffffu, mx2, o));
        float e2 = (lane < VV) ? expf(lg - mx2) : 0.f;
        float s2 = e2;
        #pragma unroll
        for (int o = 16; o > 0; o >>= 1)
            s2 += __shfl_xor_sync(0xffffffffu, s2, o);
        if (lane < VV)
            out[n * VV + lane] = lg - mx2 - logf(s2);
    }
}

// ---------------- launch ----------------
extern "C" void kernel_launch(void* const* d_in, const int* in_sizes, int n_in,
                              void* d_out, int out_size)
{
    const float* E       = (const float*)d_in[0];
    const int*   E_idx   = (const int*)  d_in[1];
    const int*   S       = (const int*)  d_in[2];
    const float* mask    = (const float*)d_in[3];
    const float* chain_M = (const float*)d_in[4];
    const float* z       = (const float*)d_in[5];
    const float* bl1     = (const float*)d_in[7];
    const float* bo1     = (const float*)d_in[13];
    const float* Wl2     = (const float*)d_in[14];
    const float* bl2     = (const float*)d_in[15];
    const float* Wr2     = (const float*)d_in[16];
    const float* br2     = (const float*)d_in[17];
    const float* We2     = (const float*)d_in[18];
    const float* be2     = (const float*)d_in[19];
    const float* a2      = (const float*)d_in[20];
    const float* bo2     = (const float*)d_in[21];
    const float* W_s     = (const float*)d_in[22];
    const float* W_out   = (const float*)d_in[23];
    const float* b_out   = (const float*)d_in[24];

    float* out = (float*)d_out;

    const int smem_bytes = (int)sizeof(SmemLayout);
    cudaFuncSetAttribute(gat_mma_kernel,
                         cudaFuncAttributeMaxDynamicSharedMemorySize, smem_bytes);

    precompute_kernel<<<32, 256>>>(bl1, bo1, Wl2, bl2, Wr2, br2, be2, bo2, We2,
                                   W_s, W_out, b_out, mask, chain_M, z);
    gat_mma_kernel<<<NN / 4, 256, smem_bytes>>>(E, E_idx, S, mask, a2, out);
}

// round 5
// speedup vs baseline: 4.6450x; 1.2264x over previous
#include <cuda_runtime.h>
#include <cuda_bf16.h>
#include <math.h>
#include <stdint.h>

#define NN 4096
#define KK 32
#define CC 128
#define VV 21
#define NTILE 1024          // NN/4 tiles of 128 rows
#define GRID 296            // 2 CTAs per SM exactly

// ---------------- precomputed tensors (device globals) ----------------
__device__ float g_base[CC];                        // bl2 + (c0@Wr2+br2) + be2
__device__ float g_u0[CC];                          // c0 @ Wl2[:C]
__device__ __nv_bfloat16 g_Tb[VV * CC];             // bf16(W_s[v] @ Wl2[C:])
__device__ float g_TW[VV][VV];                      // T @ W_out
__device__ float g_g0[VV];                          // (bl2+bo2)@W_out + b_out
__device__ float g_g1[VV];                          // u0@W_out
__device__ float g_key[NN];                         // (chain_M*mask+1e-4)*|z|
__device__ __align__(16) __nv_bfloat16 g_Bb[CC * CC]; // bf16(We2) [k][n]

// ---------------- PTX helpers (plain sm_103-legal only) ----------------
__device__ __forceinline__ uint32_t smem_u32(const void* p) {
    uint32_t a;
    asm("{ .reg .u64 t; cvta.to.shared.u64 t, %1; cvt.u32.u64 %0, t; }" : "=r"(a) : "l"(p));
    return a;
}
__device__ __forceinline__ void ldmx4(uint32_t* r, uint32_t p) {
    asm volatile("ldmatrix.sync.aligned.m8n8.x4.shared.b16 {%0,%1,%2,%3}, [%4];"
                 : "=r"(r[0]), "=r"(r[1]), "=r"(r[2]), "=r"(r[3]) : "r"(p));
}
__device__ __forceinline__ void ldmx4t(uint32_t* r, uint32_t p) {
    asm volatile("ldmatrix.sync.aligned.m8n8.x4.trans.shared.b16 {%0,%1,%2,%3}, [%4];"
                 : "=r"(r[0]), "=r"(r[1]), "=r"(r[2]), "=r"(r[3]) : "r"(p));
}
__device__ __forceinline__ void mma16816(float* d, const uint32_t* a, uint32_t b0, uint32_t b1) {
    asm volatile(
        "mma.sync.aligned.m16n8k16.row.col.f32.bf16.bf16.f32 "
        "{%0,%1,%2,%3}, {%4,%5,%6,%7}, {%8,%9}, {%0,%1,%2,%3};"
        : "+f"(d[0]), "+f"(d[1]), "+f"(d[2]), "+f"(d[3])
        : "r"(a[0]), "r"(a[1]), "r"(a[2]), "r"(a[3]), "r"(b0), "r"(b1));
}
__device__ __forceinline__ void bar_sync(int id, int cnt) {
    asm volatile("bar.sync %0, %1;" :: "r"(id), "r"(cnt) : "memory");
}
__device__ __forceinline__ void bar_arrive(int id, int cnt) {
    asm volatile("bar.arrive %0, %1;" :: "r"(id), "r"(cnt) : "memory");
}

// ---------------- precompute kernel (grid=32, block=256) ----------------
__global__ void precompute_kernel(
    const float* __restrict__ bl1, const float* __restrict__ bo1,
    const float* __restrict__ Wl2, const float* __restrict__ bl2,
    const float* __restrict__ Wr2, const float* __restrict__ br2,
    const float* __restrict__ be2, const float* __restrict__ bo2,
    const float* __restrict__ We2,
    const float* __restrict__ W_s, const float* __restrict__ W_out,
    const float* __restrict__ b_out,
    const float* __restrict__ mask, const float* __restrict__ chain_M,
    const float* __restrict__ z)
{
    __shared__ float sh0[CC];
    __shared__ float sh1[CC];
    __shared__ float sh2[CC];
    const int b = blockIdx.x;
    const int t = threadIdx.x;

    {
        int i = b * 256 + t;
        if (i < NN) {
            float cm = __fadd_rn(__fmul_rn(chain_M[i], mask[i]), 1e-4f);
            g_key[i] = __fmul_rn(cm, fabsf(z[i]));
        }
    }
    for (int i = b * 256 + t; i < CC * CC; i += 32 * 256)
        g_Bb[i] = __float2bfloat16(We2[i]);

    if (b < VV) {
        if (t < CC) {
            float acc = 0.f;
            for (int hh = 0; hh < CC; hh++)
                acc += W_s[b * CC + hh] * Wl2[(CC + hh) * CC + t];
            g_Tb[b * CC + t] = __float2bfloat16(acc);
            sh0[t] = acc;
        }
        __syncthreads();
        if (t < VV) {
            float acc = 0.f;
            for (int c = 0; c < CC; c++)
                acc += sh0[c] * W_out[c * VV + t];
            g_TW[b][t] = acc;
        }
    } else if (b == VV) {
        if (t < CC) sh0[t] = bl1[t] + bo1[t];          // c0
        __syncthreads();
        if (t < CC) {
            float u = 0.f, r = 0.f;
            for (int d = 0; d < CC; d++) {
                float c0 = sh0[d];
                u += c0 * Wl2[d * CC + t];
                r += c0 * Wr2[d * CC + t];
            }
            sh1[t] = u;  g_u0[t] = u;
            g_base[t] = bl2[t] + r + br2[t] + be2[t];
            sh2[t] = bl2[t] + bo2[t];
        }
        __syncthreads();
        if (t < VV) {
            float a0 = b_out[t], a1 = 0.f;
            for (int c = 0; c < CC; c++) {
                float wo = W_out[c * VV + t];
                a0 += sh2[c] * wo;
                a1 += sh1[c] * wo;
            }
            g_g0[t] = a0;
            g_g1[t] = a1;
        }
    }
}

// ---------------- main kernel smem ----------------
// A/B layout: 256B rows, 16B chunk j stored at j ^ (row & 7)  -> ldmatrix
// conflict-free, no padding.
struct TileBuf {
    __nv_bfloat16 A[CC * CC];   // 32 KB swizzled E tile
    float Am[4][KK];
    int   Sv[4][KK];
    float Wv[4][VV];
    float Sc[4][KK];
    float Mk[4];
};
struct Smem {
    __nv_bfloat16 B[CC * CC];   // 32 KB swizzled We2
    TileBuf buf[2];
    __nv_bfloat16 T2[VV * CC];  // bf16 T table
    float Base[CC], U0[CC], A2[CC];
    float G0[24], G1[24];
    float TW[VV][VV];
};

// barrier ids: 1+p = FULL[p], 3+p = EMPTY[p], 5 = consumer-only
#define BAR_FULL  1
#define BAR_EMPTY 3
#define BAR_CONS  5

// ---------------- main fused kernel ----------------
// 320 threads: warps 0-7 consumers (GEMM+epilogue), warps 8-9 producers.
__global__ void __launch_bounds__(320, 2) gat_mma_kernel(
    const float* __restrict__ E,
    const int*   __restrict__ E_idx,
    const int*   __restrict__ S,
    const float* __restrict__ mask,
    const float* __restrict__ a2,
    float*       __restrict__ out)
{
    extern __shared__ char raw[];
    Smem* sm = (Smem*)raw;

    const int t    = threadIdx.x;
    const int lane = t & 31;
    const int wid  = t >> 5;
    const int b    = blockIdx.x;
    const int niter = (NTILE - b + GRID - 1) / GRID;

    // ---- one-time setup: B + tables (all 320 threads) ----
    {
        const uint4* Bg = (const uint4*)g_Bb;
        for (int i = t; i < 2048; i += 320) {
            int r = i >> 4, j = i & 15;
            *(uint4*)((char*)sm->B + r * 256 + ((j ^ (r & 7)) << 4)) = Bg[i];
        }
        for (int i = t; i < VV * CC; i += 320) sm->T2[i] = g_Tb[i];
        if (t < CC) {
            sm->Base[t] = g_base[t];
            sm->U0[t]   = g_u0[t];
            sm->A2[t]   = a2[t];
        }
        if (t < VV) { sm->G0[t] = g_g0[t]; sm->G1[t] = g_g1[t]; }
        for (int i = t; i < VV * VV; i += 320)
            sm->TW[i / VV][i % VV] = g_TW[i / VV][i % VV];
    }
    __syncthreads();

    if (wid < 8) {
        // =========================== CONSUMERS ===========================
        const int m0   = wid * 16;
        const int rr   = m0 + (lane & 15);
        const int rr7  = rr & 7;
        const int ahi  = lane >> 4;                 // 0/1
        const int bsub = lane >> 3;
        const int rlow = (bsub & 1) * 8 + (lane & 7);
        const int r7b  = rlow & 7;
        const int bhi  = bsub >> 1;                 // 0/1
        const uint32_t Bb = smem_u32(sm->B) + rlow * 256;
        const uint32_t Aoff = rr * 256;

        for (int it = 0; it < niter; it++) {
            const int tile = b + it * GRID;
            const int p = it & 1;
            bar_sync(BAR_FULL + p, 320);
            TileBuf* tb = &sm->buf[p];
            const uint32_t Ab = smem_u32(tb->A) + Aoff;

            float acc[64];
            #pragma unroll
            for (int i = 0; i < 64; i++) acc[i] = 0.f;

            #pragma unroll
            for (int ks = 0; ks < 8; ks++) {
                uint32_t af[4];
                ldmx4(af, Ab + (((ks * 2 + ahi) ^ rr7) << 4));
                #pragma unroll
                for (int pp = 0; pp < 8; pp++) {
                    uint32_t bf[4];
                    ldmx4t(bf, Bb + ks * 4096 + (((pp * 2 + bhi) ^ r7b) << 4));
                    mma16816(&acc[(2 * pp) * 4],     af, bf[0], bf[1]);
                    mma16816(&acc[(2 * pp + 1) * 4], af, bf[2], bf[3]);
                }
            }

            // ---- per-row score: leaky + dot(a2) ----
            {
                const int g   = lane >> 2;
                const int h   = wid >> 1;
                const int klo = (wid & 1) * 16 + g;
                const int khi = klo + 8;
                const float aA_lo = tb->Am[h][klo];
                const float aA_hi = tb->Am[h][khi];
                const __nv_bfloat162* Tlo =
                    (const __nv_bfloat162*)&sm->T2[tb->Sv[h][klo] * CC];
                const __nv_bfloat162* Thi =
                    (const __nv_bfloat162*)&sm->T2[tb->Sv[h][khi] * CC];
                const float mk = tb->Mk[h];

                float s_lo = 0.f, s_hi = 0.f;
                #pragma unroll
                for (int nt = 0; nt < 16; nt++) {
                    const int c0 = nt * 8 + (lane & 3) * 2;
                    const float bb0 = sm->Base[c0]     + mk * sm->U0[c0];
                    const float bb1 = sm->Base[c0 + 1] + mk * sm->U0[c0 + 1];
                    const float2 tl = __bfloat1622float2(Tlo[c0 >> 1]);
                    const float2 th = __bfloat1622float2(Thi[c0 >> 1]);
                    const float a20 = sm->A2[c0], a21 = sm->A2[c0 + 1];

                    float p0 = acc[nt * 4 + 0] + bb0 + aA_lo * tl.x;
                    float p1 = acc[nt * 4 + 1] + bb1 + aA_lo * tl.y;
                    float p2 = acc[nt * 4 + 2] + bb0 + aA_hi * th.x;
                    float p3 = acc[nt * 4 + 3] + bb1 + aA_hi * th.y;
                    p0 = fmaxf(p0, 0.2f * p0);
                    p1 = fmaxf(p1, 0.2f * p1);
                    p2 = fmaxf(p2, 0.2f * p2);
                    p3 = fmaxf(p3, 0.2f * p3);
                    s_lo = fmaf(p0, a20, s_lo);
                    s_lo = fmaf(p1, a21, s_lo);
                    s_hi = fmaf(p2, a20, s_hi);
                    s_hi = fmaf(p3, a21, s_hi);
                }
                s_lo += __shfl_xor_sync(0xffffffffu, s_lo, 1);
                s_lo += __shfl_xor_sync(0xffffffffu, s_lo, 2);
                s_hi += __shfl_xor_sync(0xffffffffu, s_hi, 1);
                s_hi += __shfl_xor_sync(0xffffffffu, s_hi, 2);
                if ((lane & 3) == 0) {
                    tb->Sc[h][klo] = s_lo;
                    tb->Sc[h][khi] = s_hi;
                }
            }
            bar_sync(BAR_CONS, 256);

            // ---- softmax over k + 21-bin logits + log_softmax (warp=node) ----
            if (wid < 4) {
                const int h = wid;
                const int n = tile * 4 + h;
                const float aA = tb->Am[h][lane];
                const int   sk = tb->Sv[h][lane];

                float score = tb->Sc[h][lane];
                float mx = score;
                #pragma unroll
                for (int o = 16; o > 0; o >>= 1)
                    mx = fmaxf(mx, __shfl_xor_sync(0xffffffffu, mx, o));
                float e = expf(score - mx);
                float ssum = e;
                #pragma unroll
                for (int o = 16; o > 0; o >>= 1)
                    ssum += __shfl_xor_sync(0xffffffffu, ssum, o);
                atomicAdd(&tb->Wv[h][sk], (e / ssum) * aA);
                __syncwarp();

                float lg = -1e30f;
                if (lane < VV) {
                    lg = sm->G0[lane] + tb->Mk[h] * sm->G1[lane];
                    #pragma unroll
                    for (int u = 0; u < VV; u++)
                        lg = fmaf(tb->Wv[h][u], sm->TW[u][lane], lg);
                }
                float mx2 = lg;
                #pragma unroll
                for (int o = 16; o > 0; o >>= 1)
                    mx2 = fmaxf(mx2, __shfl_xor_sync(0xffffffffu, mx2, o));
                float e2 = (lane < VV) ? expf(lg - mx2) : 0.f;
                float s2 = e2;
                #pragma unroll
                for (int o = 16; o > 0; o >>= 1)
                    s2 += __shfl_xor_sync(0xffffffffu, s2, o);
                if (lane < VV)
                    out[n * VV + lane] = lg - mx2 - logf(s2);
            }
            bar_arrive(BAR_EMPTY + p, 320);
        }
    } else {
        // =========================== PRODUCERS ===========================
        const int tp = t - 256;                     // 0..63
        for (int it = 0; it < niter; it++) {
            const int tile = b + it * GRID;
            const int p = it & 1;
            if (it >= 2) bar_sync(BAR_EMPTY + p, 320);
            TileBuf* tb = &sm->buf[p];

            // E tile: 4096 float4 loads, cvt bf16, swizzled STS
            const float4* Eg = (const float4*)(E + (size_t)tile * (CC * CC));
            char* Ab = (char*)tb->A;
            #pragma unroll 8
            for (int s = 0; s < 64; s++) {
                const int i = tp + (s << 6);
                float4 v = Eg[i];
                const int r = i >> 5, q = i & 31;
                __nv_bfloat162 lo = __float22bfloat162_rn(make_float2(v.x, v.y));
                __nv_bfloat162 hi = __float22bfloat162_rn(make_float2(v.z, v.w));
                uint2 pk;
                pk.x = *(const uint32_t*)&lo;
                pk.y = *(const uint32_t*)&hi;
                *(uint2*)(Ab + r * 256 + (((q >> 1) ^ (r & 7)) << 4) + (q & 1) * 8) = pk;
            }
            // metadata
            #pragma unroll
            for (int i = tp; i < 128; i += 64) {
                const int h = i >> 5, k = i & 31;
                const int n = tile * 4 + h;
                const int j = E_idx[n * KK + k];
                tb->Sv[h][k] = S[j];
                float kn = g_key[n], kj = g_key[j];
                float att = (kn > kj || (kn == kj && n > j)) ? 1.f : 0.f;
                tb->Am[h][k] = mask[n] * att;
            }
            if (tp < 4) tb->Mk[tp] = mask[tile * 4 + tp];
            for (int i = tp; i < 4 * VV; i += 64) tb->Wv[i / VV][i % VV] = 0.f;

            bar_arrive(BAR_FULL + p, 320);
        }
    }
}

// ---------------- launch ----------------
extern "C" void kernel_launch(void* const* d_in, const int* in_sizes, int n_in,
                              void* d_out, int out_size)
{
    const float* E       = (const float*)d_in[0];
    const int*   E_idx   = (const int*)  d_in[1];
    const int*   S       = (const int*)  d_in[2];
    const float* mask    = (const float*)d_in[3];
    const float* chain_M = (const float*)d_in[4];
    const float* z       = (const float*)d_in[5];
    const float* bl1     = (const float*)d_in[7];
    const float* bo1     = (const float*)d_in[13];
    const float* Wl2     = (const float*)d_in[14];
    const float* bl2     = (const float*)d_in[15];
    const float* Wr2     = (const float*)d_in[16];
    const float* br2     = (const float*)d_in[17];
    const float* We2     = (const float*)d_in[18];
    const float* be2     = (const float*)d_in[19];
    const float* a2      = (const float*)d_in[20];
    const float* bo2     = (const float*)d_in[21];
    const float* W_s     = (const float*)d_in[22];
    const float* W_out   = (const float*)d_in[23];
    const float* b_out   = (const float*)d_in[24];

    float* out = (float*)d_out;

    const int smem_bytes = (int)sizeof(Smem);
    cudaFuncSetAttribute(gat_mma_kernel,
                         cudaFuncAttributeMaxDynamicSharedMemorySize, smem_bytes);

    precompute_kernel<<<32, 256>>>(bl1, bo1, Wl2, bl2, Wr2, br2, be2, bo2, We2,
                                   W_s, W_out, b_out, mask, chain_M, z);
    gat_mma_kernel<<<GRID, 320, smem_bytes>>>(E, E_idx, S, mask, a2, out);
}